// round 8
// baseline (speedup 1.0000x reference)
#include <cuda_runtime.h>
#include <cuda_fp16.h>
#include <math.h>

// ---------------- problem constants ----------------
#define LDIM   65536
#define ST     100
#define ST2    200
#define ATTD   100
#define EMBD   100
#define VOCABD 128
#define TSTEPS 258
#define GATES  400
#define MAXNB  160
#define CHMAX  512

// ---------------- device scratch ----------------
__device__ __half2 g_w1dtT2[50ull * LDIM];          // [j2][l]   13.1 MB
__device__ __half2 g_inTq[100ull * LDIM];           // [q][l]    26.2 MB
__device__ float   g_embproj[VOCABD * GATES];       // [v][r]
__device__ uint2   g_WcQ[50 * GATES];               // [u][r] packs W_ih[r][4u..4u+3]
__device__ uint2   g_WhQ[25 * GATES];               // [u][r] packs W_hh[r][4u..4u+3]
__device__ uint2   g_w2Q[50 * ATTD];                // [u][j] packs w2[j][4u..4u+3]
__device__ uint2   g_linQ[25 * VOCABD];             // [u][v] packs lin_w[v][4u..4u+3]
__device__ float2  g_ctx[2][MAXNB * ATTD];          // parity-buffered partial ctx
__device__ float   g_s[2][MAXNB];                   // parity-buffered partial exp sums
__device__ float   g_h[TSTEPS][ST];
__device__ float   g_losspart[MAXNB];
__device__ int     g_arrive;

// ---------------- helpers ----------------
__device__ __forceinline__ __half2 h2tanh_(__half2 x) {
    unsigned xi = *reinterpret_cast<unsigned*>(&x), yo;
    asm("tanh.approx.f16x2 %0, %1;" : "=r"(yo) : "r"(xi));
    return *reinterpret_cast<__half2*>(&yo);
}
__device__ __forceinline__ float sigmoidf_(float x) { return 1.f / (1.f + __expf(-x)); }
__device__ __forceinline__ __half2 u2h2(unsigned u) {
    __half2 h; *reinterpret_cast<unsigned*>(&h) = u; return h;
}
__device__ __forceinline__ unsigned packh2(float a, float b) {
    __half2 h = __floats2half2_rn(a, b); return *reinterpret_cast<unsigned*>(&h);
}
__device__ __forceinline__ float wredsum(float v) {
    #pragma unroll
    for (int o = 16; o; o >>= 1) v += __shfl_xor_sync(0xffffffffu, v, o);
    return v;
}
__device__ __forceinline__ float wredmax(float v) {
    #pragma unroll
    for (int o = 16; o; o >>= 1) v = fmaxf(v, __shfl_xor_sync(0xffffffffu, v, o));
    return v;
}

// ---------------- reset sync (runs each replay) ----------------
__global__ void k_init_sync() {
    if (blockIdx.x == 0 && threadIdx.x == 0) g_arrive = 0;
}

// ---------------- weight prep ----------------
__global__ void k_prep(const float* __restrict__ W_ih, const float* __restrict__ W_hh,
                       const float* __restrict__ b_ih, const float* __restrict__ b_hh,
                       const float* __restrict__ w2,   const float* __restrict__ lin_w,
                       const float* __restrict__ emb) {
    int gt = blockIdx.x * blockDim.x + threadIdx.x;
    int stride = gridDim.x * blockDim.x;
    for (int i = gt; i < 50 * GATES; i += stride) {
        int u = i / GATES, r = i % GATES;
        const float* p = &W_ih[r * 300 + 4 * u];
        g_WcQ[i] = make_uint2(packh2(p[0], p[1]), packh2(p[2], p[3]));
    }
    for (int i = gt; i < 25 * GATES; i += stride) {
        int u = i / GATES, r = i % GATES;
        const float* p = &W_hh[r * ST + 4 * u];
        g_WhQ[i] = make_uint2(packh2(p[0], p[1]), packh2(p[2], p[3]));
    }
    for (int i = gt; i < 50 * ATTD; i += stride) {
        int u = i / ATTD, j = i % ATTD;
        const float* p = &w2[j * ST2 + 4 * u];
        g_w2Q[i] = make_uint2(packh2(p[0], p[1]), packh2(p[2], p[3]));
    }
    for (int i = gt; i < 25 * VOCABD; i += stride) {
        int u = i / VOCABD, v = i % VOCABD;
        const float* p = &lin_w[v * ST + 4 * u];
        g_linQ[i] = make_uint2(packh2(p[0], p[1]), packh2(p[2], p[3]));
    }
    for (int i = gt; i < VOCABD * GATES; i += stride) {
        int v = i % VOCABD, r = i / VOCABD;
        float a = b_ih[r] + b_hh[r];
        const float* wrow = &W_ih[r * 300 + 200];
        const float* erow = &emb[v * EMBD];
        #pragma unroll 4
        for (int e = 0; e < EMBD; e++) a = fmaf(wrow[e], erow[e], a);
        g_embproj[v * GATES + r] = a;
    }
}

// ---------------- encoder precompute ----------------
__global__ __launch_bounds__(256, 1)
void k_enc(const float* __restrict__ inp, const float* __restrict__ w1) {
    extern __shared__ char smraw[];
    float2* w1s   = (float2*)smraw;                 // [k][j2] : 200*50 float2 = 80000 B
    __half* stage = (__half*)(smraw + 80000);       // [256][210] halfs = 107520 B
    const int tid = threadIdx.x;
    const int l0  = blockIdx.x * 256;
    const int l   = l0 + tid;

    for (int idx = tid; idx < ST2 * 50; idx += 256) {
        int k = idx / 50, j2 = idx % 50;
        w1s[idx] = make_float2(w1[(2 * j2) * ST2 + k], w1[(2 * j2 + 1) * ST2 + k]);
    }
    __syncthreads();

    float2 acc[50];
    #pragma unroll
    for (int j2 = 0; j2 < 50; j2++) acc[j2] = make_float2(0.f, 0.f);

    for (int k = 0; k < ST2; k++) {
        float x = inp[(size_t)k * LDIM + l];        // coalesced
        stage[tid * 210 + k] = __float2half(x);
        const float2* wr = &w1s[k * 50];
        #pragma unroll
        for (int j2 = 0; j2 < 50; j2++) {
            float2 w = wr[j2];
            acc[j2].x = fmaf(w.x, x, acc[j2].x);
            acc[j2].y = fmaf(w.y, x, acc[j2].y);
        }
    }
    __syncthreads();

    // [q][l] layout: g_inTq[q][l] = (in[2q][l], in[2q+1][l]) — coalesced along l
    for (int idx = tid; idx < 100 * 256; idx += 256) {
        int q = idx >> 8, r = idx & 255;
        g_inTq[(size_t)q * LDIM + l0 + r] = *(__half2*)(stage + r * 210 + 2 * q);
    }
    #pragma unroll
    for (int j2 = 0; j2 < 50; j2++)
        g_w1dtT2[(size_t)j2 * LDIM + l] = __floats2half2_rn(acc[j2].x, acc[j2].y);
}

// ---------------- persistent decoder ----------------
__global__ __launch_bounds__(512, 1)
void k_dec(const int* __restrict__ out_ids, const float* __restrict__ v_w,
           const float* __restrict__ v_b,   const float* __restrict__ lin_b,
           const int* __restrict__ eos_p,   float* __restrict__ out, int nb) {
    extern __shared__ unsigned dynsm[];
    unsigned* stageW = dynsm;                 // [l][j2] w1dt chunk: CHMAX*50 u32 = 102400 B
    uint2*    sW2    = (uint2*)(dynsm + CHMAX * 50);   // 50*100 uint2 = 40000 B

    __shared__ __align__(16) float  sscores[CHMAX];
    __shared__ __align__(16) float2 sP[5][ATTD];
    __shared__ __align__(16) float  sxf[ST2];
    __shared__ __align__(16) float4 shc4[50];     // [0..24]=h quads, [25..49]=c quads
    __shared__ __align__(16) float4 sv4[25];
    __shared__ __align__(8)  unsigned sW2Du[50];  // half2(w2dt[2j],w2dt[2j+1])
    __shared__ float  sgates[GATES];
    __shared__ float  sgpart[GATES];
    __shared__ float  sred[33];
    __shared__ float  slog[VOCABD];
    __shared__ int    s_ids[TSTEPS];
    __shared__ float  sEC[1];

    float* shcf = (float*)shc4;                   // shcf[0..99]=h, [100..199]=c

    const int b = blockIdx.x, tid = threadIdx.x;
    const int lane = tid & 31, wid = tid >> 5;
    int chunk = ((LDIM + nb - 1) / nb + 3) & ~3;  // multiple of 4 (148 -> 444)
    const int l0 = b * chunk;
    int nl = LDIM - l0; if (nl > chunk) nl = chunk; if (nl < 0) nl = 0;

    // ---- one-time setup ----
    for (int i = tid; i < TSTEPS; i += 512) s_ids[i] = out_ids[i];
    if (tid < 25) sv4[tid] = make_float4(v_w[4 * tid], v_w[4 * tid + 1],
                                         v_w[4 * tid + 2], v_w[4 * tid + 3]);
    for (int i = tid; i < 50 * ATTD; i += 512) sW2[i] = g_w2Q[i];
    // stage w1dt chunk into smem: stageW[l*50 + j2]
    for (int idx = tid; idx < nl * 50; idx += 512) {
        int j2 = idx / nl, l = idx - j2 * nl;
        stageW[l * 50 + j2] = *(const unsigned*)&g_w1dtT2[(size_t)j2 * LDIM + l0 + l];
    }
    // exp shift: C = v_b - (Sum|v| + |v_b|)  =>  p = exp(score_noVb + C) <= 1
    {
        float bb = 0.f;
        for (int i = tid; i < ATTD; i += 512) bb += fabsf(v_w[i]);
        bb = wredsum(bb);
        if (lane == 0) sred[wid] = bb;
        __syncthreads();
        if (tid == 0) {
            float s = 0.f;
            #pragma unroll
            for (int i = 0; i < 16; i++) s += sred[i];
            float vb = v_b[0];
            sEC[0] = vb - (s + fabsf(vb));
        }
        __syncthreads();
    }
    const float expC = sEC[0];
    const int eosv = eos_p[0];

    // ---- priming step (redundant in every block) ----
    if (tid < GATES) sgates[tid] = g_embproj[eosv * GATES + tid];
    __syncthreads();
    if (tid < ST) {
        float gi = sigmoidf_(sgates[tid]);
        float gg = tanhf(sgates[2 * ST + tid]);
        float go = sigmoidf_(sgates[3 * ST + tid]);
        float c = gi * gg;
        float h = go * tanhf(c);
        shcf[tid] = h; shcf[ST + tid] = c;
    }
    __syncthreads();
    // w2dt partials + gpart(step 0)
    {
        if (tid < 400) {
            const int part = tid / 100, j = tid - part * 100;
            float a = 0.f;
            #pragma unroll 5
            for (int u = part; u < 50; u += 4) {
                uint2 w = sW2[u * ATTD + j];
                float4 x = shc4[u];
                float2 f0 = __half22float2(u2h2(w.x)), f1 = __half22float2(u2h2(w.y));
                a = fmaf(f0.x, x.x, a); a = fmaf(f0.y, x.y, a);
                a = fmaf(f1.x, x.z, a); a = fmaf(f1.y, x.w, a);
            }
            sP[part][j].x = a;
            // gpart for t=0 (last = eos)
            float g = g_embproj[eosv * GATES + tid];
            #pragma unroll 5
            for (int u = 0; u < 25; u++) {
                uint2 w = __ldcg(&g_WhQ[u * GATES + tid]);
                float4 x = shc4[u];
                float2 f0 = __half22float2(u2h2(w.x)), f1 = __half22float2(u2h2(w.y));
                g = fmaf(f0.x, x.x, g); g = fmaf(f0.y, x.y, g);
                g = fmaf(f1.x, x.z, g); g = fmaf(f1.y, x.w, g);
            }
            sgpart[tid] = g;
        }
        __syncthreads();
        if (tid < 50) {
            float w0 = sP[0][2 * tid].x + sP[1][2 * tid].x + sP[2][2 * tid].x + sP[3][2 * tid].x;
            float w1_ = sP[0][2 * tid + 1].x + sP[1][2 * tid + 1].x + sP[2][2 * tid + 1].x + sP[3][2 * tid + 1].x;
            sW2Du[tid] = packh2(w0, w1_);
        }
        __syncthreads();
    }

    // ================= main decode loop =================
    for (int t = 0; t < TSTEPS; t++) {
        const int par = t & 1;

        // ---- pass A: smem-resident scores -> p, f16x2 tanh ----
        float ssum = 0.f;
        if (tid < nl) {
            const uint2* row = (const uint2*)&stageW[tid * 50];
            float sc = 0.f;
            #pragma unroll
            for (int i = 0; i < 25; i++) {
                uint2 w = row[i];
                uint2 d = *(const uint2*)&sW2Du[2 * i];
                __half2 a0 = h2tanh_(__hadd2(u2h2(w.x), u2h2(d.x)));
                __half2 a1 = h2tanh_(__hadd2(u2h2(w.y), u2h2(d.y)));
                float2 f0 = __half22float2(a0), f1 = __half22float2(a1);
                float4 vv = sv4[i];
                sc = fmaf(f0.x, vv.x, sc); sc = fmaf(f0.y, vv.y, sc);
                sc = fmaf(f1.x, vv.z, sc); sc = fmaf(f1.y, vv.w, sc);
            }
            float p = __expf(sc + expC);
            sscores[tid] = p;
            ssum = p;
        }
        ssum = wredsum(ssum);
        if (lane == 0) sred[wid] = ssum;
        __syncthreads();
        if (tid == 0) {
            float s = 0.f;
            #pragma unroll
            for (int i = 0; i < 16; i++) s += sred[i];
            g_s[par][b] = s;
        }
        __syncthreads();

        // ---- pass B: warp-per-q ctx partial, [q][l] streaming uint4 ----
        for (int q = wid; q < ATTD; q += 16) {
            const __half2* bq = g_inTq + (size_t)q * LDIM + l0;
            float ax = 0.f, ay = 0.f;
            for (int li = lane * 4; li < nl; li += 128) {
                uint4 r = *(const uint4*)(bq + li);
                float4 p4 = *(const float4*)&sscores[li];
                float2 f;
                f = __half22float2(u2h2(r.x)); ax = fmaf(p4.x, f.x, ax); ay = fmaf(p4.x, f.y, ay);
                f = __half22float2(u2h2(r.y)); ax = fmaf(p4.y, f.x, ax); ay = fmaf(p4.y, f.y, ay);
                f = __half22float2(u2h2(r.z)); ax = fmaf(p4.z, f.x, ax); ay = fmaf(p4.z, f.y, ay);
                f = __half22float2(u2h2(r.w)); ax = fmaf(p4.w, f.x, ax); ay = fmaf(p4.w, f.y, ay);
            }
            ax = wredsum(ax); ay = wredsum(ay);
            if (lane == 0) g_ctx[par][b * ATTD + q] = make_float2(ax, ay);
        }
        __threadfence();
        __syncthreads();

        // ---- single global barrier per step ----
        if (tid == 0) {
            atomicAdd(&g_arrive, 1);
            const int target = nb * (t + 1);
            while (*(volatile int*)&g_arrive < target) __nanosleep(64);
            __threadfence();
        }
        __syncthreads();

        // ---- merge partials (every block) + exp-sum reduce ----
        {
            if (tid < 500) {
                const int sub = tid / 100, q = tid - sub * 100;
                float2 acc = make_float2(0.f, 0.f);
                const float2* cp = &g_ctx[par][0];
                #pragma unroll 8
                for (int i = sub; i < nb; i += 5) {
                    float2 v = __ldcg(&cp[i * ATTD + q]);
                    acc.x += v.x; acc.y += v.y;
                }
                sP[sub][q] = acc;
            }
            float sv_ = (tid < nb) ? __ldcg(&g_s[par][tid]) : 0.f;
            sv_ = wredsum(sv_);
            if (lane == 0) sred[wid] = sv_;
        }
        __syncthreads();
        if (tid < ATTD) {
            const float Sinv = 1.f / (sred[0] + sred[1] + sred[2] + sred[3] + sred[4]);
            float2 a = sP[0][tid];
            float2 a1 = sP[1][tid], a2 = sP[2][tid], a3 = sP[3][tid], a4 = sP[4][tid];
            sxf[2 * tid]     = (a.x + a1.x + a2.x + a3.x + a4.x) * Sinv;
            sxf[2 * tid + 1] = (a.y + a1.y + a2.y + a3.y + a4.y) * Sinv;
        }
        __syncthreads();

        // ---- gates: gpart (precomputed) + Wc@ctx (L2, deep ILP) ----
        if (tid < GATES) {
            float a = sgpart[tid];
            #pragma unroll 10
            for (int u = 0; u < 50; u++) {
                uint2 w = __ldcg(&g_WcQ[u * GATES + tid]);
                float4 x = *(const float4*)&sxf[4 * u];
                float2 f0 = __half22float2(u2h2(w.x)), f1 = __half22float2(u2h2(w.y));
                a = fmaf(f0.x, x.x, a); a = fmaf(f0.y, x.y, a);
                a = fmaf(f1.x, x.z, a); a = fmaf(f1.y, x.w, a);
            }
            sgates[tid] = a;
        }
        __syncthreads();
        if (tid < ST) {
            float gi = sigmoidf_(sgates[tid]);
            float gf = sigmoidf_(sgates[ST + tid]);
            float gg = tanhf(sgates[2 * ST + tid]);
            float go = sigmoidf_(sgates[3 * ST + tid]);
            float c = fmaf(gf, shcf[ST + tid], gi * gg);
            float h = go * tanhf(c);
            shcf[tid] = h; shcf[ST + tid] = c;
            if (b == 0) g_h[t][tid] = h;
        }
        __syncthreads();

        // ---- tail: w2dt partials + gpart for next step ----
        if (tid < 400) {
            const int part = tid / 100, j = tid - part * 100;
            float a = 0.f;
            #pragma unroll 5
            for (int u = part; u < 50; u += 4) {
                uint2 w = sW2[u * ATTD + j];
                float4 x = shc4[u];
                float2 f0 = __half22float2(u2h2(w.x)), f1 = __half22float2(u2h2(w.y));
                a = fmaf(f0.x, x.x, a); a = fmaf(f0.y, x.y, a);
                a = fmaf(f1.x, x.z, a); a = fmaf(f1.y, x.w, a);
            }
            sP[part][j].x = a;
            float g = g_embproj[s_ids[t] * GATES + tid];
            #pragma unroll 5
            for (int u = 0; u < 25; u++) {
                uint2 w = __ldcg(&g_WhQ[u * GATES + tid]);
                float4 x = shc4[u];
                float2 f0 = __half22float2(u2h2(w.x)), f1 = __half22float2(u2h2(w.y));
                g = fmaf(f0.x, x.x, g); g = fmaf(f0.y, x.y, g);
                g = fmaf(f1.x, x.z, g); g = fmaf(f1.y, x.w, g);
            }
            sgpart[tid] = g;
        }
        __syncthreads();
        if (tid < 50) {
            float w0 = sP[0][2 * tid].x + sP[1][2 * tid].x + sP[2][2 * tid].x + sP[3][2 * tid].x;
            float w1_ = sP[0][2 * tid + 1].x + sP[1][2 * tid + 1].x + sP[2][2 * tid + 1].x + sP[3][2 * tid + 1].x;
            sW2Du[tid] = packh2(w0, w1_);
        }
        __syncthreads();
    }

    // ---- make block-0's g_h writes globally visible, then barrier ----
    __threadfence();
    __syncthreads();
    if (tid == 0) {
        atomicAdd(&g_arrive, 1);
        while (*(volatile int*)&g_arrive < nb * (TSTEPS + 1)) __nanosleep(64);
        __threadfence();
    }
    __syncthreads();

    // ---- deferred losses: steps distributed across blocks ----
    float myloss = 0.f;
    for (int t = b; t < TSTEPS; t += nb) {
        if (tid < ST) shcf[tid] = __ldcg(&g_h[t][tid]);
        __syncthreads();
        if (tid < VOCABD) {
            float a = lin_b[tid];
            #pragma unroll
            for (int u = 0; u < 25; u++) {
                uint2 w = __ldcg(&g_linQ[u * VOCABD + tid]);
                float4 x = shc4[u];
                float2 f0 = __half22float2(u2h2(w.x)), f1 = __half22float2(u2h2(w.y));
                a = fmaf(f0.x, x.x, a); a = fmaf(f0.y, x.y, a);
                a = fmaf(f1.x, x.z, a); a = fmaf(f1.y, x.w, a);
            }
            slog[tid] = a;
            float m = wredmax(a);
            if (lane == 0) sred[wid] = m;
        }
        __syncthreads();
        if (tid == 0)
            sred[32] = fmaxf(fmaxf(sred[0], sred[1]), fmaxf(sred[2], sred[3]));
        __syncthreads();
        const float M = sred[32];
        if (tid < VOCABD) {
            float e = __expf(slog[tid] - M);
            e = wredsum(e);
            if (lane == 0) sred[16 + wid] = e;
        }
        __syncthreads();
        if (tid == 0) {
            float S2 = sred[16] + sred[17] + sred[18] + sred[19];
            int ch = s_ids[t];
            myloss += (M + logf(S2)) - slog[ch];
        }
        __syncthreads();
    }
    if (tid == 0) g_losspart[b] = myloss;
    __threadfence();
    __syncthreads();
    if (tid == 0) atomicAdd(&g_arrive, 1);
    if (b == 0) {
        if (tid == 0) {
            while (*(volatile int*)&g_arrive < nb * (TSTEPS + 2)) __nanosleep(64);
            __threadfence();
        }
        __syncthreads();
        float v = (tid < nb) ? g_losspart[tid] : 0.f;
        v = wredsum(v);
        if (lane == 0) sred[wid] = v;
        __syncthreads();
        if (tid == 0) {
            float s = 0.f;
            #pragma unroll
            for (int i = 0; i < 16; i++) s += sred[i];
            out[0] = s;
        }
    }
}

// ---------------- launch ----------------
extern "C" void kernel_launch(void* const* d_in, const int* in_sizes, int n_in,
                              void* d_out, int out_size) {
    const float* input_mat = (const float*)d_in[0];
    const int*   out_ids   = (const int*)  d_in[1];
    const float* W_ih      = (const float*)d_in[2];
    const float* W_hh      = (const float*)d_in[3];
    const float* b_ih      = (const float*)d_in[4];
    const float* b_hh      = (const float*)d_in[5];
    const float* w1        = (const float*)d_in[6];
    const float* w2        = (const float*)d_in[7];
    const float* v_w       = (const float*)d_in[8];
    const float* v_b       = (const float*)d_in[9];
    const float* lin_w     = (const float*)d_in[10];
    const float* lin_b     = (const float*)d_in[11];
    const float* emb       = (const float*)d_in[12];
    const int*   eos_id    = (const int*)  d_in[13];
    float* out = (float*)d_out;

    int nb = 148;
    cudaDeviceGetAttribute(&nb, cudaDevAttrMultiProcessorCount, 0);
    if (nb > MAXNB) nb = MAXNB;

    const int decSmem = CHMAX * 50 * 4 + 50 * ATTD * 8;   // 102400 + 40000 = 142400
    cudaFuncSetAttribute(k_enc, cudaFuncAttributeMaxDynamicSharedMemorySize, 187520);
    cudaFuncSetAttribute(k_dec, cudaFuncAttributeMaxDynamicSharedMemorySize, decSmem);

    k_init_sync<<<1, 32>>>();
    k_prep<<<120, 256>>>(W_ih, W_hh, b_ih, b_hh, w2, lin_w, emb);
    k_enc<<<LDIM / 256, 256, 187520>>>(input_mat, w1);
    k_dec<<<nb, 512, decSmem>>>(out_ids, v_w, v_b, lin_b, eos_id, out, nb);
}

// round 9
// speedup vs baseline: 1.1834x; 1.1834x over previous
#include <cuda_runtime.h>
#include <cuda_fp16.h>
#include <math.h>

// ---------------- problem constants ----------------
#define LDIM   65536
#define ST     100
#define ST2    200
#define ATTD   100
#define EMBD   100
#define VOCABD 128
#define TSTEPS 258
#define GATES  400
#define MAXNB  160
#define CHMAX  512

// ---------------- device scratch ----------------
__device__ __half2 g_w1dtT2[50ull * LDIM];          // [j2][l]   13.1 MB
__device__ __half2 g_inT2[(size_t)LDIM * 100];      // [l][q]    26.2 MB
__device__ float   g_embproj[VOCABD * GATES];       // [v][r]
__device__ uint2   g_WcQ[50 * GATES];               // [u][r] packs W_ih[r][4u..4u+3]
__device__ uint2   g_WhQ[25 * GATES];               // [u][r] packs W_hh[r][4u..4u+3]
__device__ uint2   g_w2Q[50 * ATTD];                // [u][j] packs w2[j][4u..4u+3]
__device__ uint2   g_linQ[25 * VOCABD];             // [u][v] packs lin_w[v][4u..4u+3]
__device__ float2  g_ctx[2][MAXNB * ATTD];          // parity-buffered partial ctx
__device__ float   g_s[2][MAXNB];                   // parity-buffered partial exp sums
__device__ float   g_h[TSTEPS][ST];
__device__ float   g_losspart[MAXNB];
__device__ int     g_arrive;

// ---------------- helpers ----------------
__device__ __forceinline__ __half2 h2tanh_(__half2 x) {
    unsigned xi = *reinterpret_cast<unsigned*>(&x), yo;
    asm("tanh.approx.f16x2 %0, %1;" : "=r"(yo) : "r"(xi));
    return *reinterpret_cast<__half2*>(&yo);
}
__device__ __forceinline__ float sigmoidf_(float x) { return 1.f / (1.f + __expf(-x)); }
__device__ __forceinline__ __half2 u2h2(unsigned u) {
    __half2 h; *reinterpret_cast<unsigned*>(&h) = u; return h;
}
__device__ __forceinline__ unsigned packh2(float a, float b) {
    __half2 h = __floats2half2_rn(a, b); return *reinterpret_cast<unsigned*>(&h);
}
__device__ __forceinline__ float wredsum(float v) {
    #pragma unroll
    for (int o = 16; o; o >>= 1) v += __shfl_xor_sync(0xffffffffu, v, o);
    return v;
}
__device__ __forceinline__ float wredmax(float v) {
    #pragma unroll
    for (int o = 16; o; o >>= 1) v = fmaxf(v, __shfl_xor_sync(0xffffffffu, v, o));
    return v;
}

// ---------------- reset sync (runs each replay) ----------------
__global__ void k_init_sync() {
    if (blockIdx.x == 0 && threadIdx.x == 0) g_arrive = 0;
}

// ---------------- weight prep ----------------
__global__ void k_prep(const float* __restrict__ W_ih, const float* __restrict__ W_hh,
                       const float* __restrict__ b_ih, const float* __restrict__ b_hh,
                       const float* __restrict__ w2,   const float* __restrict__ lin_w,
                       const float* __restrict__ emb) {
    int gt = blockIdx.x * blockDim.x + threadIdx.x;
    int stride = gridDim.x * blockDim.x;
    for (int i = gt; i < 50 * GATES; i += stride) {
        int u = i / GATES, r = i % GATES;
        const float* p = &W_ih[r * 300 + 4 * u];
        g_WcQ[i] = make_uint2(packh2(p[0], p[1]), packh2(p[2], p[3]));
    }
    for (int i = gt; i < 25 * GATES; i += stride) {
        int u = i / GATES, r = i % GATES;
        const float* p = &W_hh[r * ST + 4 * u];
        g_WhQ[i] = make_uint2(packh2(p[0], p[1]), packh2(p[2], p[3]));
    }
    for (int i = gt; i < 50 * ATTD; i += stride) {
        int u = i / ATTD, j = i % ATTD;
        const float* p = &w2[j * ST2 + 4 * u];
        g_w2Q[i] = make_uint2(packh2(p[0], p[1]), packh2(p[2], p[3]));
    }
    for (int i = gt; i < 25 * VOCABD; i += stride) {
        int u = i / VOCABD, v = i % VOCABD;
        const float* p = &lin_w[v * ST + 4 * u];
        g_linQ[i] = make_uint2(packh2(p[0], p[1]), packh2(p[2], p[3]));
    }
    for (int i = gt; i < VOCABD * GATES; i += stride) {
        int v = i % VOCABD, r = i / VOCABD;
        float a = b_ih[r] + b_hh[r];
        const float* wrow = &W_ih[r * 300 + 200];
        const float* erow = &emb[v * EMBD];
        #pragma unroll 4
        for (int e = 0; e < EMBD; e++) a = fmaf(wrow[e], erow[e], a);
        g_embproj[v * GATES + r] = a;
    }
}

// ---------------- encoder precompute ----------------
__global__ __launch_bounds__(256, 1)
void k_enc(const float* __restrict__ inp, const float* __restrict__ w1) {
    extern __shared__ char smraw[];
    float2* w1s   = (float2*)smraw;                 // [k][j2] : 200*50 float2 = 80000 B
    __half* stage = (__half*)(smraw + 80000);       // [256][210] halfs = 107520 B
    const int tid = threadIdx.x;
    const int l0  = blockIdx.x * 256;
    const int l   = l0 + tid;

    for (int idx = tid; idx < ST2 * 50; idx += 256) {
        int k = idx / 50, j2 = idx % 50;
        w1s[idx] = make_float2(w1[(2 * j2) * ST2 + k], w1[(2 * j2 + 1) * ST2 + k]);
    }
    __syncthreads();

    float2 acc[50];
    #pragma unroll
    for (int j2 = 0; j2 < 50; j2++) acc[j2] = make_float2(0.f, 0.f);

    for (int k = 0; k < ST2; k++) {
        float x = inp[(size_t)k * LDIM + l];        // coalesced
        stage[tid * 210 + k] = __float2half(x);
        const float2* wr = &w1s[k * 50];
        #pragma unroll
        for (int j2 = 0; j2 < 50; j2++) {
            float2 w = wr[j2];
            acc[j2].x = fmaf(w.x, x, acc[j2].x);
            acc[j2].y = fmaf(w.y, x, acc[j2].y);
        }
    }
    __syncthreads();

    // [l][q] layout: g_inT2[l][q] = (in[2q][l], in[2q+1][l])
    for (int idx = tid; idx < 256 * 100; idx += 256) {
        int r = idx / 100, q = idx % 100;
        g_inT2[(size_t)(l0 + r) * 100 + q] = *(__half2*)(stage + r * 210 + 2 * q);
    }
    #pragma unroll
    for (int j2 = 0; j2 < 50; j2++)
        g_w1dtT2[(size_t)j2 * LDIM + l] = __floats2half2_rn(acc[j2].x, acc[j2].y);
}

// ---------------- persistent decoder ----------------
__global__ __launch_bounds__(512, 1)
void k_dec(const int* __restrict__ out_ids, const float* __restrict__ v_w,
           const float* __restrict__ v_b,   const float* __restrict__ lin_b,
           const int* __restrict__ eos_p,   float* __restrict__ out, int nb) {
    extern __shared__ uint2 dynsm[];
    uint2* sWc = dynsm;                  // 50*400 uint2 = 160000 B
    uint2* sW2 = dynsm + 50 * GATES;     // 50*100 uint2 = 40000 B

    __shared__ __align__(16) float  sscores[CHMAX];
    __shared__ __align__(16) float2 sP[5][ATTD];
    __shared__ __align__(16) float4 sx4[50];
    __shared__ __align__(16) float4 shc4[50];     // [0..24]=h quads, [25..49]=c quads
    __shared__ __align__(8)  float2 sv2[50];      // v_w pairs
    __shared__ __align__(8)  unsigned sW2Du[50];  // half2(w2dt[2j],w2dt[2j+1])
    __shared__ float  sgates[GATES];
    __shared__ float  sred[33];
    __shared__ float  slog[VOCABD];
    __shared__ int    s_ids[TSTEPS];
    __shared__ float  sEC[1];

    float* shcf = (float*)shc4;                   // shcf[0..99]=h, [100..199]=c
    float* sxf  = (float*)sx4;                    // sxf[0..199] = merged ctx

    const int b = blockIdx.x, tid = threadIdx.x;
    const int lane = tid & 31, wid = tid >> 5;
    int chunk = ((LDIM + nb - 1) / nb + 3) & ~3;  // multiple of 4 (148 -> 444)
    const int l0 = b * chunk;
    int nl = LDIM - l0; if (nl > chunk) nl = chunk; if (nl < 0) nl = 0;

    // ---- one-time setup ----
    for (int i = tid; i < TSTEPS; i += 512) s_ids[i] = out_ids[i];
    if (tid < 50) sv2[tid] = make_float2(v_w[2 * tid], v_w[2 * tid + 1]);
    for (int i = tid; i < 50 * GATES; i += 512) sWc[i] = g_WcQ[i];
    for (int i = tid; i < 50 * ATTD;  i += 512) sW2[i] = g_w2Q[i];
    // exp shift: C = v_b - (Sum|v| + |v_b|)  =>  p = exp(score_noVb + C) <= 1
    {
        float bb = 0.f;
        for (int i = tid; i < ATTD; i += 512) bb += fabsf(v_w[i]);
        bb = wredsum(bb);
        if (lane == 0) sred[wid] = bb;
        __syncthreads();
        if (tid == 0) {
            float s = 0.f;
            #pragma unroll
            for (int i = 0; i < 16; i++) s += sred[i];
            float vb = v_b[0];
            sEC[0] = vb - (s + fabsf(vb));
        }
        __syncthreads();
    }
    const float expC = sEC[0];
    const int eosv = eos_p[0];
    int lastid = eosv;

    // ---- priming step (redundant in every block) ----
    if (tid < GATES) sgates[tid] = g_embproj[eosv * GATES + tid];
    __syncthreads();
    if (tid < ST) {
        float gi = sigmoidf_(sgates[tid]);
        float gg = tanhf(sgates[2 * ST + tid]);
        float go = sigmoidf_(sgates[3 * ST + tid]);
        float c = gi * gg;
        float h = go * tanhf(c);
        shcf[tid] = h; shcf[ST + tid] = c;
    }
    __syncthreads();
    // w2dt partials -> packed half2 sW2Du
    {
        if (tid < 400) {
            const int part = tid / 100, j = tid - part * 100;
            float a = 0.f;
            #pragma unroll 5
            for (int u = part; u < 50; u += 4) {
                uint2 w = sW2[u * ATTD + j];
                float4 x = shc4[u];
                float2 f0 = __half22float2(u2h2(w.x)), f1 = __half22float2(u2h2(w.y));
                a = fmaf(f0.x, x.x, a); a = fmaf(f0.y, x.y, a);
                a = fmaf(f1.x, x.z, a); a = fmaf(f1.y, x.w, a);
            }
            sP[part][j].x = a;
        }
        __syncthreads();
        if (tid < 50) {
            float w0  = sP[0][2 * tid].x + sP[1][2 * tid].x + sP[2][2 * tid].x + sP[3][2 * tid].x;
            float w1_ = sP[0][2 * tid + 1].x + sP[1][2 * tid + 1].x + sP[2][2 * tid + 1].x + sP[3][2 * tid + 1].x;
            sW2Du[tid] = packh2(w0, w1_);
        }
        __syncthreads();
    }

    // ================= main decode loop =================
    for (int t = 0; t < TSTEPS; t++) {
        const int par = t & 1;

        // ---- pass A: scores -> p, f16x2 tanh, L2 streaming ----
        float ssum = 0.f;
        if (tid < nl) {
            const size_t lg = (size_t)(l0 + tid);
            float sc = 0.f;
            #pragma unroll 10
            for (int j2 = 0; j2 < 50; j2++) {
                unsigned w = __ldcg((const unsigned*)&g_w1dtT2[(size_t)j2 * LDIM] + lg);
                __half2 a2 = h2tanh_(__hadd2(u2h2(w), u2h2(sW2Du[j2])));
                float2 f = __half22float2(a2);
                float2 vv = sv2[j2];
                sc = fmaf(f.x, vv.x, sc);
                sc = fmaf(f.y, vv.y, sc);
            }
            float p = __expf(sc + expC);
            sscores[tid] = p;
            ssum = p;
        }
        ssum = wredsum(ssum);
        if (lane == 0) sred[wid] = ssum;
        __syncthreads();
        if (tid == 0) {
            float s = 0.f;
            #pragma unroll
            for (int i = 0; i < 16; i++) s += sred[i];
            g_s[par][b] = s;
        }
        __syncthreads();

        // ---- pass B: partial ctx over this chunk (4 l-segments x 100 k-pairs) ----
        {
            const int seg = tid / 100, q = tid - seg * 100;
            if (tid < 400) {
                int seglen = (nl + 3) >> 2;
                int ls = seg * seglen, le = ls + seglen;
                if (le > nl) le = nl;
                if (ls > nl) ls = nl;
                float2 acc = make_float2(0.f, 0.f);
                const __half2* base = g_inT2 + (size_t)l0 * 100 + q;
                #pragma unroll 8
                for (int li = ls; li < le; li++) {
                    float p = sscores[li];
                    float2 f = __half22float2(__ldcg(&base[(size_t)li * 100]));
                    acc.x = fmaf(p, f.x, acc.x);
                    acc.y = fmaf(p, f.y, acc.y);
                }
                sP[seg][q] = acc;
            }
        }
        __syncthreads();
        if (tid < ATTD) {
            float2 a0 = sP[0][tid], a1 = sP[1][tid], a2 = sP[2][tid], a3 = sP[3][tid];
            g_ctx[par][b * ATTD + tid] = make_float2((a0.x + a1.x) + (a2.x + a3.x),
                                                     (a0.y + a1.y) + (a2.y + a3.y));
        }
        __threadfence();
        __syncthreads();

        // ---- single global barrier per step (pure spin) ----
        if (tid == 0) {
            atomicAdd(&g_arrive, 1);
            const int target = nb * (t + 1);
            while (*(volatile int*)&g_arrive < target) { }
            __threadfence();
        }
        __syncthreads();

        // ---- merge partials (every block, MLP-8) + exp-sum reduce ----
        {
            if (tid < 500) {
                const int sub = tid / 100, q = tid - sub * 100;
                float2 acc = make_float2(0.f, 0.f);
                const float2* cp = &g_ctx[par][0];
                #pragma unroll 8
                for (int i = sub; i < nb; i += 5) {
                    float2 v = __ldcg(&cp[i * ATTD + q]);
                    acc.x += v.x; acc.y += v.y;
                }
                sP[sub][q] = acc;
            }
            float sv_ = (tid < nb) ? __ldcg(&g_s[par][tid]) : 0.f;
            sv_ = wredsum(sv_);
            if (lane == 0) sred[wid] = sv_;
        }
        __syncthreads();
        if (tid < ATTD) {
            const float Sinv = 1.f / (sred[0] + sred[1] + sred[2] + sred[3] + sred[4]);
            float2 a = sP[0][tid];
            float2 a1 = sP[1][tid], a2 = sP[2][tid], a3 = sP[3][tid], a4 = sP[4][tid];
            sxf[2 * tid]     = (a.x + a1.x + a2.x + a3.x + a4.x) * Sinv;
            sxf[2 * tid + 1] = (a.y + a1.y + a2.y + a3.y + a4.y) * Sinv;
        }
        __syncthreads();

        // ---- gates: Wc (smem) + Wh (L2, fully unrolled for MLP) ----
        if (tid < GATES) {
            float a = g_embproj[lastid * GATES + tid];
            #pragma unroll 10
            for (int u = 0; u < 50; u++) {
                uint2 w = sWc[u * GATES + tid];
                float4 x = sx4[u];
                float2 f0 = __half22float2(u2h2(w.x)), f1 = __half22float2(u2h2(w.y));
                a = fmaf(f0.x, x.x, a); a = fmaf(f0.y, x.y, a);
                a = fmaf(f1.x, x.z, a); a = fmaf(f1.y, x.w, a);
            }
            #pragma unroll
            for (int u = 0; u < 25; u++) {
                uint2 w = __ldcg(&g_WhQ[u * GATES + tid]);
                float4 x = shc4[u];               // h quads (prev step)
                float2 f0 = __half22float2(u2h2(w.x)), f1 = __half22float2(u2h2(w.y));
                a = fmaf(f0.x, x.x, a); a = fmaf(f0.y, x.y, a);
                a = fmaf(f1.x, x.z, a); a = fmaf(f1.y, x.w, a);
            }
            sgates[tid] = a;
        }
        __syncthreads();
        if (tid < ST) {
            float gi = sigmoidf_(sgates[tid]);
            float gf = sigmoidf_(sgates[ST + tid]);
            float gg = tanhf(sgates[2 * ST + tid]);
            float go = sigmoidf_(sgates[3 * ST + tid]);
            float c = fmaf(gf, shcf[ST + tid], gi * gg);
            float h = go * tanhf(c);
            shcf[tid] = h; shcf[ST + tid] = c;
            if (b == 0) g_h[t][tid] = h;
        }
        __syncthreads();

        // ---- tail: w2dt partials for next step ----
        if (tid < 400) {
            const int part = tid / 100, j = tid - part * 100;
            float a = 0.f;
            #pragma unroll 5
            for (int u = part; u < 50; u += 4) {
                uint2 w = sW2[u * ATTD + j];
                float4 x = shc4[u];
                float2 f0 = __half22float2(u2h2(w.x)), f1 = __half22float2(u2h2(w.y));
                a = fmaf(f0.x, x.x, a); a = fmaf(f0.y, x.y, a);
                a = fmaf(f1.x, x.z, a); a = fmaf(f1.y, x.w, a);
            }
            sP[part][j].x = a;
        }
        __syncthreads();
        if (tid < 50) {
            float w0  = sP[0][2 * tid].x + sP[1][2 * tid].x + sP[2][2 * tid].x + sP[3][2 * tid].x;
            float w1_ = sP[0][2 * tid + 1].x + sP[1][2 * tid + 1].x + sP[2][2 * tid + 1].x + sP[3][2 * tid + 1].x;
            sW2Du[tid] = packh2(w0, w1_);
        }
        lastid = s_ids[t];
        __syncthreads();
    }

    // ---- make block-0's g_h writes globally visible, then barrier ----
    __threadfence();
    __syncthreads();
    if (tid == 0) {
        atomicAdd(&g_arrive, 1);
        while (*(volatile int*)&g_arrive < nb * (TSTEPS + 1)) { }
        __threadfence();
    }
    __syncthreads();

    // ---- deferred losses: steps distributed across blocks ----
    float myloss = 0.f;
    for (int t = b; t < TSTEPS; t += nb) {
        if (tid < ST) shcf[tid] = __ldcg(&g_h[t][tid]);
        __syncthreads();
        if (tid < VOCABD) {
            float a = lin_b[tid];
            #pragma unroll
            for (int u = 0; u < 25; u++) {
                uint2 w = __ldcg(&g_linQ[u * VOCABD + tid]);
                float4 x = shc4[u];
                float2 f0 = __half22float2(u2h2(w.x)), f1 = __half22float2(u2h2(w.y));
                a = fmaf(f0.x, x.x, a); a = fmaf(f0.y, x.y, a);
                a = fmaf(f1.x, x.z, a); a = fmaf(f1.y, x.w, a);
            }
            slog[tid] = a;
            float m = wredmax(a);
            if (lane == 0) sred[wid] = m;
        }
        __syncthreads();
        if (tid == 0)
            sred[32] = fmaxf(fmaxf(sred[0], sred[1]), fmaxf(sred[2], sred[3]));
        __syncthreads();
        const float M = sred[32];
        if (tid < VOCABD) {
            float e = __expf(slog[tid] - M);
            e = wredsum(e);
            if (lane == 0) sred[16 + wid] = e;
        }
        __syncthreads();
        if (tid == 0) {
            float S2 = sred[16] + sred[17] + sred[18] + sred[19];
            int ch = s_ids[t];
            myloss += (M + logf(S2)) - slog[ch];
        }
        __syncthreads();
    }
    if (tid == 0) g_losspart[b] = myloss;
    __threadfence();
    __syncthreads();
    if (tid == 0) atomicAdd(&g_arrive, 1);
    if (b == 0) {
        if (tid == 0) {
            while (*(volatile int*)&g_arrive < nb * (TSTEPS + 2)) { }
            __threadfence();
        }
        __syncthreads();
        float v = (tid < nb) ? g_losspart[tid] : 0.f;
        v = wredsum(v);
        if (lane == 0) sred[wid] = v;
        __syncthreads();
        if (tid == 0) {
            float s = 0.f;
            #pragma unroll
            for (int i = 0; i < 16; i++) s += sred[i];
            out[0] = s;
        }
    }
}

// ---------------- launch ----------------
extern "C" void kernel_launch(void* const* d_in, const int* in_sizes, int n_in,
                              void* d_out, int out_size) {
    const float* input_mat = (const float*)d_in[0];
    const int*   out_ids   = (const int*)  d_in[1];
    const float* W_ih      = (const float*)d_in[2];
    const float* W_hh      = (const float*)d_in[3];
    const float* b_ih      = (const float*)d_in[4];
    const float* b_hh      = (const float*)d_in[5];
    const float* w1        = (const float*)d_in[6];
    const float* w2        = (const float*)d_in[7];
    const float* v_w       = (const float*)d_in[8];
    const float* v_b       = (const float*)d_in[9];
    const float* lin_w     = (const float*)d_in[10];
    const float* lin_b     = (const float*)d_in[11];
    const float* emb       = (const float*)d_in[12];
    const int*   eos_id    = (const int*)  d_in[13];
    float* out = (float*)d_out;

    int nb = 148;
    cudaDeviceGetAttribute(&nb, cudaDevAttrMultiProcessorCount, 0);
    if (nb > MAXNB) nb = MAXNB;

    cudaFuncSetAttribute(k_enc, cudaFuncAttributeMaxDynamicSharedMemorySize, 187520);
    cudaFuncSetAttribute(k_dec, cudaFuncAttributeMaxDynamicSharedMemorySize, 200000);

    k_init_sync<<<1, 32>>>();
    k_prep<<<120, 256>>>(W_ih, W_hh, b_ih, b_hh, w2, lin_w, emb);
    k_enc<<<LDIM / 256, 256, 187520>>>(input_mat, w1);
    k_dec<<<nb, 512, 200000>>>(out_ids, v_w, v_b, lin_b, eos_id, out, nb);
}